// round 1
// baseline (speedup 1.0000x reference)
#include <cuda_runtime.h>

// Problem constants
#define NN 32768   // rows
#define DD 160     // input dim
#define FF 128     // number of networks
#define HH 32      // hidden dim

// Tiling
#define ROWS 256        // rows per block
#define NTHREADS 256
#define XP 161          // Xs pitch (8*161 mod 32 = 8 -> conflict-free strided row loads)
#define HP 33           // h1s pitch (8*33 mod 32 = 8 -> conflict-free)

// smem layout sizes (floats)
#define XS_SZ   (ROWS * XP)        // 41216
#define W1_SZ   (DD * HH)          // 5120
#define H1_SZ   (ROWS * HP)        // 8448
#define W2_SZ   (HH * HH)          // 1024
#define TAIL_SZ (HH + HH + HH + 4) // b1, b2, W3, b3(+pad)
#define SMEM_FLOATS (XS_SZ + W1_SZ + H1_SZ + W2_SZ + TAIL_SZ)
#define SMEM_BYTES  (SMEM_FLOATS * 4)

__device__ __forceinline__ float elu_f(float v) {
    return v > 0.0f ? v : expm1f(v);
}

__global__ void __launch_bounds__(NTHREADS, 1)
ensemble_mlp_kernel(const float* __restrict__ X,
                    const float* __restrict__ W1,
                    const float* __restrict__ b1,
                    const float* __restrict__ W2,
                    const float* __restrict__ b2,
                    const float* __restrict__ W3,
                    const float* __restrict__ b3,
                    float* __restrict__ out)
{
    extern __shared__ float smem[];
    float* Xs  = smem;                 // [ROWS][XP]
    float* W1s = Xs  + XS_SZ;          // [DD][HH]  (k-major, h contiguous)
    float* h1s = W1s + W1_SZ;          // [ROWS][HP]
    float* W2s = h1s + H1_SZ;          // [HH][HH]  (k-major, h contiguous)
    float* b1s = W2s + W2_SZ;          // [HH]
    float* b2s = b1s + HH;             // [HH]
    float* W3s = b2s + HH;             // [HH]
    float* b3s = W3s + HH;             // [1]

    const int f    = blockIdx.y;
    const int row0 = blockIdx.x * ROWS;
    const int tid  = threadIdx.x;

    // ---- load per-network weights ----
    {
        const float4* W1g = (const float4*)(W1 + (size_t)f * DD * HH);
        #pragma unroll
        for (int i = tid; i < W1_SZ / 4; i += NTHREADS)
            ((float4*)W1s)[i] = W1g[i];
        const float4* W2g = (const float4*)(W2 + (size_t)f * HH * HH);
        for (int i = tid; i < W2_SZ / 4; i += NTHREADS)
            ((float4*)W2s)[i] = W2g[i];
        if (tid < HH)            b1s[tid]          = b1[f * HH + tid];
        else if (tid < 2 * HH)   b2s[tid - HH]     = b2[f * HH + (tid - HH)];
        else if (tid < 3 * HH)   W3s[tid - 2 * HH] = W3[f * HH + (tid - 2 * HH)];
        else if (tid == 3 * HH)  b3s[0]            = b3[f];
    }

    // ---- load X tile (row-major, padded pitch) ----
    {
        const float4* Xg = (const float4*)(X + (size_t)row0 * DD);
        const int nvec = ROWS * (DD / 4);   // 10240
        for (int i = tid; i < nvec; i += NTHREADS) {
            int r  = i / (DD / 4);
            int c4 = i % (DD / 4);
            float4 v = Xg[(size_t)r * (DD / 4) + c4];
            float* dst = Xs + r * XP + c4 * 4;
            dst[0] = v.x; dst[1] = v.y; dst[2] = v.z; dst[3] = v.w;
        }
    }
    __syncthreads();

    // thread tile: 8 rows x 4 hidden cols
    const int tc = tid & 7;        // 0..7  -> cols tc*4 .. tc*4+3
    const int tr = tid >> 3;       // 0..31 -> rows tr*8 .. tr*8+7
    const int c0 = tc * 4;
    const float* xrow = Xs + (tr * 8) * XP;

    float acc[8][4];

    // ================= Layer 1: h1 = elu(X @ W1 + b1) =================
    {
        float bb0 = b1s[c0 + 0], bb1 = b1s[c0 + 1], bb2 = b1s[c0 + 2], bb3 = b1s[c0 + 3];
        #pragma unroll
        for (int i = 0; i < 8; i++) {
            acc[i][0] = bb0; acc[i][1] = bb1; acc[i][2] = bb2; acc[i][3] = bb3;
        }
        #pragma unroll 4
        for (int k = 0; k < DD; k++) {
            float4 w = *(const float4*)(W1s + k * HH + c0);
            #pragma unroll
            for (int i = 0; i < 8; i++) {
                float x = xrow[i * XP + k];
                acc[i][0] += x * w.x;
                acc[i][1] += x * w.y;
                acc[i][2] += x * w.z;
                acc[i][3] += x * w.w;
            }
        }
        #pragma unroll
        for (int i = 0; i < 8; i++) {
            int r = tr * 8 + i;
            #pragma unroll
            for (int j = 0; j < 4; j++)
                h1s[r * HP + c0 + j] = elu_f(acc[i][j]);
        }
    }
    // layer-2 reads only rows written by this same warp (tr-groups are warp-local)
    __syncwarp();

    // ================= Layer 2: h2 = elu(h1 @ W2 + b2) =================
    {
        float bb0 = b2s[c0 + 0], bb1 = b2s[c0 + 1], bb2 = b2s[c0 + 2], bb3 = b2s[c0 + 3];
        #pragma unroll
        for (int i = 0; i < 8; i++) {
            acc[i][0] = bb0; acc[i][1] = bb1; acc[i][2] = bb2; acc[i][3] = bb3;
        }
        const float* hrow = h1s + (tr * 8) * HP;
        #pragma unroll
        for (int k = 0; k < HH; k++) {
            float4 w = *(const float4*)(W2s + k * HH + c0);
            #pragma unroll
            for (int i = 0; i < 8; i++) {
                float x = hrow[i * HP + k];
                acc[i][0] += x * w.x;
                acc[i][1] += x * w.y;
                acc[i][2] += x * w.z;
                acc[i][3] += x * w.w;
            }
        }
    }

    // ================= Layer 3: out = h2 . W3 + b3  (reduce over 8 tc lanes) ====
    {
        float w30 = W3s[c0 + 0], w31 = W3s[c0 + 1], w32 = W3s[c0 + 2], w33 = W3s[c0 + 3];
        float bias3 = b3s[0];
        #pragma unroll
        for (int i = 0; i < 8; i++) {
            float s = elu_f(acc[i][0]) * w30
                    + elu_f(acc[i][1]) * w31
                    + elu_f(acc[i][2]) * w32
                    + elu_f(acc[i][3]) * w33;
            s += __shfl_xor_sync(0xffffffffu, s, 1);
            s += __shfl_xor_sync(0xffffffffu, s, 2);
            s += __shfl_xor_sync(0xffffffffu, s, 4);
            if (tc == 0) {
                int n = row0 + tr * 8 + i;
                out[(size_t)n * FF + f] = s + bias3;
            }
        }
    }
}

extern "C" void kernel_launch(void* const* d_in, const int* in_sizes, int n_in,
                              void* d_out, int out_size)
{
    const float* X  = (const float*)d_in[0];
    const float* W1 = (const float*)d_in[1];
    const float* b1 = (const float*)d_in[2];
    const float* W2 = (const float*)d_in[3];
    const float* b2 = (const float*)d_in[4];
    const float* W3 = (const float*)d_in[5];
    const float* b3 = (const float*)d_in[6];
    float* out = (float*)d_out;

    static int configured = 0;
    if (!configured) {
        cudaFuncSetAttribute(ensemble_mlp_kernel,
                             cudaFuncAttributeMaxDynamicSharedMemorySize,
                             SMEM_BYTES);
        configured = 1;
    }

    dim3 grid(NN / ROWS, FF);   // (128 row-tiles, 128 networks)
    ensemble_mlp_kernel<<<grid, NTHREADS, SMEM_BYTES>>>(X, W1, b1, W2, b2, W3, b3, out);
}

// round 3
// speedup vs baseline: 3.7421x; 3.7421x over previous
#include <cuda_runtime.h>
#include <cuda_bf16.h>
#include <cstdint>

// ---------------- problem constants ----------------
#define NN 32768
#define DD 160     // = 10 k-steps of 16
#define FF 128
#define HH 32      // = 4 n-tiles of 8 = 2 k-steps of 16
#define KS1 10     // layer-1 k-steps
#define ROWS 256   // rows per CTA
#define NMT 16     // m-tiles per CTA (256/16)
#define NF 16      // networks per CTA
#define NTHR 256

#define GMT (NN / 16)              // 2048 global m-tiles
#define WBLK 25088                 // per-f weight block bytes

// ---------------- device scratch (no allocs) ----------------
__device__ __align__(16) uint4 g_XfragH[(size_t)GMT * KS1 * 32];   // 10.5 MB
__device__ __align__(16) uint4 g_XfragL[(size_t)GMT * KS1 * 32];   // 10.5 MB
__device__ __align__(16) unsigned char g_Wblk[(size_t)FF * WBLK];  // 3.2 MB
// per-f block layout: W1H[1280]u2 @0 | W1L @10240 | W2H[256]u2 @20480 | W2L @22528 | misc 128 floats @24576

// ---------------- helpers ----------------
__device__ __forceinline__ uint32_t smem_u32(const void* p) {
    uint32_t a;
    asm("{ .reg .u64 t; cvta.to.shared.u64 t, %1; cvt.u32.u64 %0, t; }" : "=r"(a) : "l"(p));
    return a;
}
#define MBARRIER_INIT(addr, cnt) \
    asm volatile("mbarrier.init.shared.b64 [%0], %1;" :: "r"((uint32_t)(addr)), "r"((uint32_t)(cnt)) : "memory")
#define MBARRIER_EXPECT_TX(addr, bytes) \
    asm volatile("mbarrier.arrive.expect_tx.shared.b64 _, [%0], %1;" :: "r"((uint32_t)(addr)), "r"((uint32_t)(bytes)) : "memory")
#define MBARRIER_WAIT_PARITY(mbar_smem_addr, phase_parity) do { \
    uint32_t _mbar = (uint32_t)(mbar_smem_addr); \
    uint32_t _parity = (uint32_t)(phase_parity); \
    uint32_t _done; \
    asm volatile("{\n\t.reg .pred p;\n\t" \
        "mbarrier.try_wait.parity.acquire.cta.shared::cta.b64 p, [%1], %2;\n\t" \
        "selp.b32 %0, 1, 0, p;\n\t}" : "=r"(_done) : "r"(_mbar), "r"(_parity) : "memory"); \
    if (!_done) { \
        asm volatile("{\n\t.reg .pred P1;\n\t" \
            "WAIT_LOOP_%=:\n\t" \
            "mbarrier.try_wait.parity.acquire.cta.shared::cta.b64 P1, [%0], %1, 0x989680;\n\t" \
            "@P1 bra.uni WAIT_DONE_%=;\n\t" \
            "bra.uni WAIT_LOOP_%=;\n\t" \
            "WAIT_DONE_%=:\n\t}" :: "r"(_mbar), "r"(_parity) : "memory"); \
    } \
} while (0)
#define BULK_G2S(dst_smem, src_gmem, bytes, mbar) \
    asm volatile("cp.async.bulk.shared::cluster.global.mbarrier::complete_tx::bytes [%0], [%1], %2, [%3];" \
        :: "r"((uint32_t)(dst_smem)), "l"(src_gmem), "r"((uint32_t)(bytes)), "r"((uint32_t)(mbar)) : "memory")

// mma.m16n8k16 row.col f32.bf16.bf16.f32 (sm_80+ PTX; no 'a' features)
__device__ __forceinline__ void mma16816(float* c, const uint32_t* a, uint32_t b0, uint32_t b1) {
    asm volatile("mma.sync.aligned.m16n8k16.row.col.f32.bf16.bf16.f32 "
        "{%0,%1,%2,%3}, {%4,%5,%6,%7}, {%8,%9}, {%0,%1,%2,%3};"
        : "+f"(c[0]), "+f"(c[1]), "+f"(c[2]), "+f"(c[3])
        : "r"(a[0]), "r"(a[1]), "r"(a[2]), "r"(a[3]), "r"(b0), "r"(b1));
}

__device__ __forceinline__ float elu_f(float v) { return v > 0.0f ? v : (__expf(v) - 1.0f); }

__device__ __forceinline__ uint32_t pack_hi2(float x, float y, float& lx, float& ly) {
    __nv_bfloat162 h = __floats2bfloat162_rn(x, y);
    lx = x - __bfloat162float(h.x);
    ly = y - __bfloat162float(h.y);
    return *reinterpret_cast<uint32_t*>(&h);
}
__device__ __forceinline__ uint32_t pack2(float x, float y) {
    __nv_bfloat162 h = __floats2bfloat162_rn(x, y);
    return *reinterpret_cast<uint32_t*>(&h);
}

// ---------------- prep: X -> A-fragment order, bf16 hi/lo ----------------
// fragment (m16n8k16 A): gid=lane>>2, tig=lane&3
//   a0={X[gid][tig*2..+1]}, a1={X[gid+8][..]}, a2={X[gid][tig*2+8..]}, a3={X[gid+8][+8..]}
__global__ void prep_x_kernel(const float* __restrict__ X) {
    int gmt = blockIdx.x;
    int t = threadIdx.x;            // 0..319
    int s = t >> 5, lane = t & 31;
    int gid = lane >> 2, tig = lane & 3;
    int r0 = gmt * 16 + gid;
    int c0 = s * 16 + tig * 2;
    float2 v00 = *(const float2*)(X + (size_t)r0 * DD + c0);
    float2 v10 = *(const float2*)(X + (size_t)(r0 + 8) * DD + c0);
    float2 v01 = *(const float2*)(X + (size_t)r0 * DD + c0 + 8);
    float2 v11 = *(const float2*)(X + (size_t)(r0 + 8) * DD + c0 + 8);
    float l00x, l00y, l10x, l10y, l01x, l01y, l11x, l11y;
    uint4 H, L;
    H.x = pack_hi2(v00.x, v00.y, l00x, l00y);
    H.y = pack_hi2(v10.x, v10.y, l10x, l10y);
    H.z = pack_hi2(v01.x, v01.y, l01x, l01y);
    H.w = pack_hi2(v11.x, v11.y, l11x, l11y);
    L.x = pack2(l00x, l00y);
    L.y = pack2(l10x, l10y);
    L.z = pack2(l01x, l01y);
    L.w = pack2(l11x, l11y);
    size_t idx = ((size_t)gmt * KS1 + s) * 32 + lane;
    g_XfragH[idx] = H;
    g_XfragL[idx] = L;
}

// ---------------- prep: W -> B-fragment order + misc, bf16 hi/lo ----------------
// B frag: b0={W[k0+tig*2][n], W[k0+tig*2+1][n]}, b1={W[k0+tig*2+8][n], W[k0+tig*2+9][n]}, n=nt*8+gid
__global__ void prep_w_kernel(const float* __restrict__ W1, const float* __restrict__ W2,
                              const float* __restrict__ b1, const float* __restrict__ b2,
                              const float* __restrict__ W3, const float* __restrict__ b3) {
    int f = blockIdx.x;
    unsigned char* blk = g_Wblk + (size_t)f * WBLK;
    uint2* w1h = (uint2*)blk;
    uint2* w1l = (uint2*)(blk + 10240);
    uint2* w2h = (uint2*)(blk + 20480);
    uint2* w2l = (uint2*)(blk + 22528);
    float* misc = (float*)(blk + 24576);

    const float* W1f = W1 + (size_t)f * DD * HH;
    for (int i = threadIdx.x; i < KS1 * 4 * 32; i += blockDim.x) {   // 1280
        int s = i >> 7, nt = (i >> 5) & 3, lane = i & 31;
        int gid = lane >> 2, tig = lane & 3;
        int n = nt * 8 + gid, k0 = s * 16 + tig * 2;
        float w00 = W1f[k0 * HH + n],       w01 = W1f[(k0 + 1) * HH + n];
        float w10 = W1f[(k0 + 8) * HH + n], w11 = W1f[(k0 + 9) * HH + n];
        float l0x, l0y, l1x, l1y;
        uint32_t h0 = pack_hi2(w00, w01, l0x, l0y);
        uint32_t h1 = pack_hi2(w10, w11, l1x, l1y);
        w1h[i] = make_uint2(h0, h1);
        w1l[i] = make_uint2(pack2(l0x, l0y), pack2(l1x, l1y));
    }
    const float* W2f = W2 + (size_t)f * HH * HH;
    for (int i = threadIdx.x; i < 2 * 4 * 32; i += blockDim.x) {     // 256
        int s = i >> 7, nt = (i >> 5) & 3, lane = i & 31;
        int gid = lane >> 2, tig = lane & 3;
        int n = nt * 8 + gid, k0 = s * 16 + tig * 2;
        float w00 = W2f[k0 * HH + n],       w01 = W2f[(k0 + 1) * HH + n];
        float w10 = W2f[(k0 + 8) * HH + n], w11 = W2f[(k0 + 9) * HH + n];
        float l0x, l0y, l1x, l1y;
        uint32_t h0 = pack_hi2(w00, w01, l0x, l0y);
        uint32_t h1 = pack_hi2(w10, w11, l1x, l1y);
        w2h[i] = make_uint2(h0, h1);
        w2l[i] = make_uint2(pack2(l0x, l0y), pack2(l1x, l1y));
    }
    int t = threadIdx.x;
    if (t < HH)            misc[t]      = b1[f * HH + t];
    else if (t < 2 * HH)   misc[t]      = b2[f * HH + (t - HH)];
    else if (t < 3 * HH)   misc[t]      = W3[f * HH + (t - 2 * HH)];
    else if (t == 3 * HH)  misc[96]     = b3[f];
    else if (t < 128)      misc[t]      = 0.0f;
}

// ---------------- main kernel ----------------
#define SM_XH 0
#define SM_XL 81920
#define SM_W  163840            // two WBLK buffers
#define SM_MBX (163840 + 2 * WBLK)       // 214016
#define SM_MBW0 (SM_MBX + 8)
#define SM_MBW1 (SM_MBX + 16)
#define SMEM_DYN (SM_MBX + 32)           // 214048

__global__ void __launch_bounds__(NTHR, 1)
mlp_main_kernel(float* __restrict__ out) {
    extern __shared__ unsigned char smem[];
    const uint32_t sb = smem_u32(smem);

    const int tile = blockIdx.x;        // 0..127
    const int f0   = blockIdx.y * NF;   // base network
    const int tid  = threadIdx.x;
    const int wid  = tid >> 5;
    const int lane = tid & 31;
    const int gid  = lane >> 2, tig = lane & 3;
    const int mtg0 = wid * 2;           // this warp's first m-tile (of 16)

    if (tid == 0) {
        MBARRIER_INIT(sb + SM_MBX, 1);
        MBARRIER_INIT(sb + SM_MBW0, 1);
        MBARRIER_INIT(sb + SM_MBW1, 1);
    }
    __syncthreads();
    if (tid == 0) {
        MBARRIER_EXPECT_TX(sb + SM_MBX, 163840u);
        BULK_G2S(sb + SM_XH, (const void*)(g_XfragH + (size_t)tile * NMT * KS1 * 32), 81920u, sb + SM_MBX);
        BULK_G2S(sb + SM_XL, (const void*)(g_XfragL + (size_t)tile * NMT * KS1 * 32), 81920u, sb + SM_MBX);
        MBARRIER_EXPECT_TX(sb + SM_MBW0, (uint32_t)WBLK);
        BULK_G2S(sb + SM_W, (const void*)(g_Wblk + (size_t)f0 * WBLK), (uint32_t)WBLK, sb + SM_MBW0);
        MBARRIER_EXPECT_TX(sb + SM_MBW1, (uint32_t)WBLK);
        BULK_G2S(sb + SM_W + WBLK, (const void*)(g_Wblk + (size_t)(f0 + 1) * WBLK), (uint32_t)WBLK, sb + SM_MBW1);
    }

    const uint4* XH = (const uint4*)(smem + SM_XH);
    const uint4* XL = (const uint4*)(smem + SM_XL);

    MBARRIER_WAIT_PARITY(sb + SM_MBX, 0);

    #pragma unroll 1
    for (int j = 0; j < NF; j++) {
        MBARRIER_WAIT_PARITY(sb + SM_MBW0 + (j & 1) * 8, (j >> 1) & 1);
        const unsigned char* wb = smem + SM_W + (j & 1) * WBLK;
        const uint2* W1H = (const uint2*)wb;
        const uint2* W1L = (const uint2*)(wb + 10240);
        const uint2* W2H = (const uint2*)(wb + 20480);
        const uint2* W2L = (const uint2*)(wb + 22528);
        const float* misc = (const float*)(wb + 24576);

        // ---------- layer 1 ----------
        float acc[2][4][4];
        #pragma unroll
        for (int nt = 0; nt < 4; nt++) {
            float bc0 = misc[nt * 8 + tig * 2];
            float bc1 = misc[nt * 8 + tig * 2 + 1];
            #pragma unroll
            for (int mt = 0; mt < 2; mt++) {
                acc[mt][nt][0] = bc0; acc[mt][nt][1] = bc1;
                acc[mt][nt][2] = bc0; acc[mt][nt][3] = bc1;
            }
        }
        #pragma unroll
        for (int s = 0; s < KS1; s++) {
            uint4 Ah0 = XH[((mtg0 + 0) * KS1 + s) * 32 + lane];
            uint4 Ah1 = XH[((mtg0 + 1) * KS1 + s) * 32 + lane];
            uint4 Al0 = XL[((mtg0 + 0) * KS1 + s) * 32 + lane];
            uint4 Al1 = XL[((mtg0 + 1) * KS1 + s) * 32 + lane];
            #pragma unroll
            for (int nt = 0; nt < 4; nt++) {
                uint2 bh = W1H[(s * 4 + nt) * 32 + lane];
                uint2 bl = W1L[(s * 4 + nt) * 32 + lane];
                mma16816(acc[0][nt], (const uint32_t*)&Ah0, bh.x, bh.y);
                mma16816(acc[1][nt], (const uint32_t*)&Ah1, bh.x, bh.y);
                mma16816(acc[0][nt], (const uint32_t*)&Ah0, bl.x, bl.y);
                mma16816(acc[1][nt], (const uint32_t*)&Ah1, bl.x, bl.y);
                mma16816(acc[0][nt], (const uint32_t*)&Al0, bh.x, bh.y);
                mma16816(acc[1][nt], (const uint32_t*)&Al1, bh.x, bh.y);
            }
        }

        // ---------- L1 epilogue: elu + split -> layer-2 A frags (in registers) ----------
        // layer2 A frag [mt][s2][4]:  nt even -> regs 0,1 ; nt odd -> regs 2,3 ; s2 = nt>>1
        uint32_t a2H[2][2][4], a2L[2][2][4];
        #pragma unroll
        for (int mt = 0; mt < 2; mt++) {
            #pragma unroll
            for (int nt = 0; nt < 4; nt++) {
                float v0 = elu_f(acc[mt][nt][0]);
                float v1 = elu_f(acc[mt][nt][1]);
                float v2 = elu_f(acc[mt][nt][2]);
                float v3 = elu_f(acc[mt][nt][3]);
                int s2 = nt >> 1, r = (nt & 1) * 2;
                float lx, ly;
                a2H[mt][s2][r + 0] = pack_hi2(v0, v1, lx, ly);
                a2L[mt][s2][r + 0] = pack2(lx, ly);
                a2H[mt][s2][r + 1] = pack_hi2(v2, v3, lx, ly);
                a2L[mt][s2][r + 1] = pack2(lx, ly);
            }
        }

        // ---------- layer 2 ----------
        float acc2[2][4][4];
        #pragma unroll
        for (int nt = 0; nt < 4; nt++) {
            float bc0 = misc[32 + nt * 8 + tig * 2];
            float bc1 = misc[32 + nt * 8 + tig * 2 + 1];
            #pragma unroll
            for (int mt = 0; mt < 2; mt++) {
                acc2[mt][nt][0] = bc0; acc2[mt][nt][1] = bc1;
                acc2[mt][nt][2] = bc0; acc2[mt][nt][3] = bc1;
            }
        }
        #pragma unroll
        for (int s2 = 0; s2 < 2; s2++) {
            #pragma unroll
            for (int nt = 0; nt < 4; nt++) {
                uint2 bh = W2H[(s2 * 4 + nt) * 32 + lane];
                uint2 bl = W2L[(s2 * 4 + nt) * 32 + lane];
                mma16816(acc2[0][nt], a2H[0][s2], bh.x, bh.y);
                mma16816(acc2[1][nt], a2H[1][s2], bh.x, bh.y);
                mma16816(acc2[0][nt], a2H[0][s2], bl.x, bl.y);
                mma16816(acc2[1][nt], a2H[1][s2], bl.x, bl.y);
                mma16816(acc2[0][nt], a2L[0][s2], bh.x, bh.y);
                mma16816(acc2[1][nt], a2L[1][s2], bh.x, bh.y);
            }
        }

        // ---------- layer 3: dot with W3, reduce over tig quad ----------
        {
            float b3v = misc[96];
            const int f = f0 + j;
            #pragma unroll
            for (int mt = 0; mt < 2; mt++) {
                float s0 = 0.0f, s1 = 0.0f;
                #pragma unroll
                for (int nt = 0; nt < 4; nt++) {
                    float w0 = misc[64 + nt * 8 + tig * 2];
                    float w1 = misc[64 + nt * 8 + tig * 2 + 1];
                    s0 += elu_f(acc2[mt][nt][0]) * w0 + elu_f(acc2[mt][nt][1]) * w1;
                    s1 += elu_f(acc2[mt][nt][2]) * w0 + elu_f(acc2[mt][nt][3]) * w1;
                }
                s0 += __shfl_xor_sync(0xffffffffu, s0, 1);
                s0 += __shfl_xor_sync(0xffffffffu, s0, 2);
                s1 += __shfl_xor_sync(0xffffffffu, s1, 1);
                s1 += __shfl_xor_sync(0xffffffffu, s1, 2);
                if (tig == 0) {
                    int row = tile * ROWS + (mtg0 + mt) * 16 + gid;
                    out[(size_t)row * FF + f]       = s0 + b3v;
                    out[(size_t)(row + 8) * FF + f] = s1 + b3v;
                }
            }
        }

        __syncthreads();   // all warps done reading this W buffer
        if (tid == 0 && j < NF - 2) {
            uint32_t mb = sb + SM_MBW0 + (j & 1) * 8;
            MBARRIER_EXPECT_TX(mb, (uint32_t)WBLK);
            BULK_G2S(sb + SM_W + (j & 1) * WBLK,
                     (const void*)(g_Wblk + (size_t)(f0 + j + 2) * WBLK),
                     (uint32_t)WBLK, mb);
        }
    }
}

// ---------------- launch ----------------
extern "C" void kernel_launch(void* const* d_in, const int* in_sizes, int n_in,
                              void* d_out, int out_size) {
    const float* X  = (const float*)d_in[0];
    const float* W1 = (const float*)d_in[1];
    const float* b1 = (const float*)d_in[2];
    const float* W2 = (const float*)d_in[3];
    const float* b2 = (const float*)d_in[4];
    const float* W3 = (const float*)d_in[5];
    const float* b3 = (const float*)d_in[6];
    float* out = (float*)d_out;

    static int configured = 0;
    if (!configured) {
        cudaFuncSetAttribute(mlp_main_kernel,
                             cudaFuncAttributeMaxDynamicSharedMemorySize, SMEM_DYN);
        configured = 1;
    }

    prep_x_kernel<<<GMT, 320>>>(X);
    prep_w_kernel<<<FF, 256>>>(W1, W2, b1, b2, W3, b3);
    dim3 grid(NN / ROWS, FF / NF);     // (128, 8)
    mlp_main_kernel<<<grid, NTHR, SMEM_DYN>>>(out);
}